// round 15
// baseline (speedup 1.0000x reference)
#include <cuda_runtime.h>
#include <math.h>
#include <stdint.h>

#define NR 32768
#define DM 256
#define NLAY 3
#define NSTEP 4
#define FFD 512
#define VOC 4096
#define KL 8

// weight split region offsets (floats)
#define OFF_QKV 0
#define OFF_AO  589824
#define OFF_F1  786432
#define OFF_F2  1179648
#define W_TOTAL 1572864

// smem: 2 buffers x (A1 4096 | A2 4096 | B1 2048 | B2 2048) floats
#define SMEM_MMA (2 * 12288 * 4)   // 98304 bytes

// ---------------- persistent device scratch ----------------
__device__ float g_xt[NR * 4];
__device__ float g_code[NR];
__device__ int   g_gid[NR];
__device__ int   g_bin[NR];
__device__ float g_h[NR * DM];
__device__ float g_qbuf[NR * DM];
__device__ float g_d1[NR * DM];
__device__ float g_kc[NLAY * NSTEP * NR * DM];
__device__ float g_vc[NLAY * NSTEP * NR * DM];
__device__ float g_w1[W_TOTAL];
__device__ float g_w2[W_TOTAL];
// fragment-ordered tf32 split activation buffers
__device__ float g_hA1[NR * DM];
__device__ float g_hA2[NR * DM];
__device__ float g_rA1[NR * DM];
__device__ float g_rA2[NR * DM];
__device__ float g_aA1[NR * DM];
__device__ float g_aA2[NR * DM];
__device__ float g_dA1[NR * FFD];
__device__ float g_dA2[NR * FFD];
__device__ float g_z[NR * 9];
__device__ float g_zarr[NSTEP * NR];
__device__ float g_qarr[NSTEP * NR];
__device__ float g_Hc[VOC * KL];
__device__ float g_Hm1[VOC];
__device__ float g_rat[VOC * KL];
__device__ float2 g_ropetab[NSTEP * 128];
__device__ unsigned g_mm[2];
__device__ float g_pdot[128];
__device__ float g_pclip[128];
__device__ float g_pvq[128];
__device__ float g_uni;

// ---------------- helpers ----------------
__device__ __forceinline__ unsigned f2u(float f) {
    unsigned u = __float_as_uint(f);
    return (u & 0x80000000u) ? ~u : (u | 0x80000000u);
}
__device__ __forceinline__ float u2f(unsigned u) {
    u = (u & 0x80000000u) ? (u & 0x7fffffffu) : ~u;
    return __uint_as_float(u);
}
__device__ __forceinline__ float tf32r(float a) {
    uint32_t u;
    asm("cvt.rna.tf32.f32 %0, %1;" : "=r"(u) : "f"(a));
    return __uint_as_float(u);
}
__device__ __forceinline__ void mma8(float* d, const uint32_t* a, const uint32_t* b) {
    asm volatile(
        "mma.sync.aligned.m16n8k8.row.col.f32.tf32.tf32.f32 "
        "{%0,%1,%2,%3}, {%4,%5,%6,%7}, {%8,%9}, {%0,%1,%2,%3};"
        : "+f"(d[0]), "+f"(d[1]), "+f"(d[2]), "+f"(d[3])
        : "r"(a[0]), "r"(a[1]), "r"(a[2]), "r"(a[3]), "r"(b[0]), "r"(b[1]));
}
__device__ __forceinline__ void cpa16(uint32_t dst, const void* src) {
    asm volatile("cp.async.ca.shared.global [%0], [%1], 16;" :: "r"(dst), "l"(src) : "memory");
}
// fragment slot for A element (m,k) with consumer K/8 == Ks (4 floats per lane: a0,a1,a2,a3)
__device__ __forceinline__ int fragdst(int m, int k, int Ks) {
    return (((m >> 4) * Ks + (k >> 3)) << 7)
         + (((m & 7) * 4 + (k & 3)) << 2)
         + ((m >> 3) & 1) + (((k >> 2) & 1) << 1);
}
__device__ __forceinline__ void store_split(float* d1, float* d2, int m, int k, int Ks, float v) {
    float hi = tf32r(v);
    float lo = tf32r(v - hi);
    int dst = fragdst(m, k, Ks);
    d1[dst] = hi;
    d2[dst] = lo;
}

// ---------------- init ----------------
__global__ void k_init(const float* __restrict__ x, const float* __restrict__ pw,
                       const float* __restrict__ pb, const float* __restrict__ rat0) {
    int n = blockIdx.x * blockDim.x + threadIdx.x;
    if (n < NR) {
        int b = n >> 10, l = n & 1023;
        const float* xb = x + (size_t)b * 32768 + l;
        #pragma unroll
        for (int j = 0; j < 4; j++) {
            float acc = pb[j];
            #pragma unroll
            for (int cz = 0; cz < 32; cz++) acc += xb[cz * 1024] * pw[j * 32 + cz];
            g_xt[n * 4 + j] = tanhf(acc);
        }
        g_code[n] = 0.f;
        g_gid[n] = 0;
    }
    if (n < VOC * KL) g_rat[n] = rat0[n];
    if (n < NSTEP * 128) {
        int pos = n >> 7, j = n & 127;
        float inv = powf(10000.f, -(float)(2 * j) / 256.f);
        float ang = (float)pos * inv;
        g_ropetab[n] = make_float2(cosf(ang), sinf(ang));
    }
    if (n == 0) g_uni = 0.f;
}

// ---------------- weight split into tf32 hi/lo, MMA-FRAGMENT order (B side) ----------------
__global__ void k_splitw2(const float* __restrict__ src, float* __restrict__ d1,
                          float* __restrict__ d2, int Nn, int Kk) {
    int i = blockIdx.x * 256 + threadIdx.x;
    if (i >= Nn * Kk) return;
    int n = i / Kk, k = i % Kk;
    float v = src[i];
    float w1 = tf32r(v);
    float w2 = tf32r(v - w1);
    int dst = (((n >> 3) * (Kk >> 3) + (k >> 3)) * 64) + ((n & 7) * 4 + ((k & 7) & 3)) * 2 + ((k & 7) >> 2);
    d1[dst] = w1;
    d2[dst] = w2;
}

// ---------------- embed: h linear + plain split + rope split ----------------
__global__ void k_embed(const float* __restrict__ in_w, const float* __restrict__ in_b, int step) {
    int idx = blockIdx.x * blockDim.x + threadIdx.x;
    int n = idx >> 8, d = idx & 255;
    float v = g_code[n] * in_w[2 * d] + g_xt[n * 4 + step] * in_w[2 * d + 1] + in_b[d];
    g_h[idx] = v;
    store_split(g_hA1, g_hA2, n, d, 32, v);
    float p = __shfl_xor_sync(0xffffffffu, v, 1);
    float2 cs = g_ropetab[step * 128 + (d >> 1)];
    float sgn = (d & 1) ? 1.f : -1.f;
    float vr = v * cs.x + sgn * p * cs.y;
    store_split(g_rA1, g_rA2, n, d, 32, vr);
}

// ---------------- pure cp.async + mma GEMM (3-term dual-acc, frag-ordered operands) ----
// C[M,N] = A[M,K] @ W[N,K]^T + bias; CTA tile 128x64, 256 threads,
// warp grid 4(M)x2(N), warp tile 32x32 via m16n8k8.
// Single __syncthreads per chunk: wait -> sync -> issue(c+1) -> mma(c).
__global__ void __launch_bounds__(256, 2) k_gemm_mma(
    const float* __restrict__ Ah1, const float* __restrict__ Ah2,
    const float* __restrict__ Ar1, const float* __restrict__ Ar2,
    const float* __restrict__ W1, const float* __restrict__ W2,
    const float* __restrict__ bias,
    float* __restrict__ C0, float* __restrict__ C1, float* __restrict__ C2,
    int seg, int N, int K, int relu, int ropeN,
    int osplit, float* __restrict__ O1, float* __restrict__ O2, int oKs) {
    extern __shared__ float smf[];
    const int tid = threadIdx.x;
    const int bm = blockIdx.y * 128;
    const int bn = blockIdx.x * 64;
    const float* A1g = (bn < ropeN) ? Ar1 : Ah1;
    const float* A2g = (bn < ropeN) ? Ar2 : Ah2;
    const int warp = tid >> 5, lane = tid & 31;
    const int rr = lane >> 2, cc = lane & 3;
    const int Ks = K >> 3;
    const int nC = K >> 5;
    const int wnb = (warp >> 2) * 4;
    const int abg0 = bm >> 4;
    const int nbg0 = bn >> 3;

    float accH[2][4][4], accC[2][4][4];
    #pragma unroll
    for (int mt = 0; mt < 2; mt++)
        #pragma unroll
        for (int nt = 0; nt < 4; nt++)
            #pragma unroll
            for (int q = 0; q < 4; q++) { accH[mt][nt][q] = 0.f; accC[mt][nt][q] = 0.f; }

    // prologue: issue chunk 0 into buffer 0
    {
        float* A1p = smf;
        #pragma unroll
        for (int i = 0; i < 4; i++) {
            int f4 = tid + i * 256;
            int ab = f4 >> 7, rem = f4 & 127;
            size_t src = ((size_t)(abg0 + ab) * Ks) * 128 + rem * 4;
            cpa16((uint32_t)__cvta_generic_to_shared(A1p + f4 * 4), A1g + src);
            cpa16((uint32_t)__cvta_generic_to_shared(A1p + 4096 + f4 * 4), A2g + src);
        }
        #pragma unroll
        for (int i = 0; i < 2; i++) {
            int f4 = tid + i * 256;
            int nb = f4 >> 6, rem = f4 & 63;
            size_t src = ((size_t)(nbg0 + nb) * Ks) * 64 + rem * 4;
            cpa16((uint32_t)__cvta_generic_to_shared(A1p + 8192 + f4 * 4), W1 + src);
            cpa16((uint32_t)__cvta_generic_to_shared(A1p + 10240 + f4 * 4), W2 + src);
        }
        asm volatile("cp.async.commit_group;" ::: "memory");
    }

    for (int c = 0; c < nC; c++) {
        const int buf = c & 1;
        float* A1p = smf + buf * 12288;
        float* A2p = A1p + 4096;
        float* B1p = A1p + 8192;
        float* B2p = A1p + 10240;

        asm volatile("cp.async.wait_group 0;" ::: "memory");
        __syncthreads();   // also proves all warps finished mma(c-1) on buf^1

        if (c + 1 < nC) {
            float* nA1 = smf + (buf ^ 1) * 12288;
            int sg0 = (c + 1) * 4;
            #pragma unroll
            for (int i = 0; i < 4; i++) {
                int f4 = tid + i * 256;
                int ab = f4 >> 7, rem = f4 & 127;
                size_t src = ((size_t)(abg0 + ab) * Ks + sg0) * 128 + rem * 4;
                cpa16((uint32_t)__cvta_generic_to_shared(nA1 + f4 * 4), A1g + src);
                cpa16((uint32_t)__cvta_generic_to_shared(nA1 + 4096 + f4 * 4), A2g + src);
            }
            #pragma unroll
            for (int i = 0; i < 2; i++) {
                int f4 = tid + i * 256;
                int nb = f4 >> 6, rem = f4 & 63;
                size_t src = ((size_t)(nbg0 + nb) * Ks + sg0) * 64 + rem * 4;
                cpa16((uint32_t)__cvta_generic_to_shared(nA1 + 8192 + f4 * 4), W1 + src);
                cpa16((uint32_t)__cvta_generic_to_shared(nA1 + 10240 + f4 * 4), W2 + src);
            }
            asm volatile("cp.async.commit_group;" ::: "memory");
        }

        #pragma unroll
        for (int s = 0; s < 4; s++) {
            uint32_t bf1[4][2], bf2[4][2];
            #pragma unroll
            for (int nt = 0; nt < 4; nt++) {
                int ob = (((wnb + nt) * 4 + s) * 32 + lane) * 2;
                float2 t1 = *(float2*)(B1p + ob);
                float2 t2 = *(float2*)(B2p + ob);
                bf1[nt][0] = __float_as_uint(t1.x); bf1[nt][1] = __float_as_uint(t1.y);
                bf2[nt][0] = __float_as_uint(t2.x); bf2[nt][1] = __float_as_uint(t2.y);
            }
            #pragma unroll
            for (int mt = 0; mt < 2; mt++) {
                int mb = (warp & 3) * 2 + mt;
                int oa = ((mb * 4 + s) * 32 + lane) * 4;
                float4 f1 = *(float4*)(A1p + oa);
                uint32_t af1[4] = {__float_as_uint(f1.x), __float_as_uint(f1.y),
                                   __float_as_uint(f1.z), __float_as_uint(f1.w)};
                #pragma unroll
                for (int nt = 0; nt < 4; nt++) mma8(accH[mt][nt], af1, bf1[nt]);
                #pragma unroll
                for (int nt = 0; nt < 4; nt++) mma8(accC[mt][nt], af1, bf2[nt]);
            }
            #pragma unroll
            for (int mt = 0; mt < 2; mt++) {
                int mb = (warp & 3) * 2 + mt;
                int oa = ((mb * 4 + s) * 32 + lane) * 4;
                float4 f2v = *(float4*)(A2p + oa);
                uint32_t af2[4] = {__float_as_uint(f2v.x), __float_as_uint(f2v.y),
                                   __float_as_uint(f2v.z), __float_as_uint(f2v.w)};
                #pragma unroll
                for (int nt = 0; nt < 4; nt++) mma8(accC[mt][nt], af2, bf1[nt]);
            }
        }
    }

    // epilogue: out = accH + accC + bias
    #pragma unroll
    for (int mt = 0; mt < 2; mt++) {
        int row0 = bm + (warp & 3) * 32 + mt * 16 + rr;
        #pragma unroll
        for (int nt = 0; nt < 4; nt++) {
            int col = bn + (warp >> 2) * 32 + nt * 8 + 2 * cc;
            float bx = bias[col], by = bias[col + 1];
            float v00 = accH[mt][nt][0] + accC[mt][nt][0] + bx;
            float v01 = accH[mt][nt][1] + accC[mt][nt][1] + by;
            float v10 = accH[mt][nt][2] + accC[mt][nt][2] + bx;
            float v11 = accH[mt][nt][3] + accC[mt][nt][3] + by;
            if (relu) {
                v00 = fmaxf(v00, 0.f); v01 = fmaxf(v01, 0.f);
                v10 = fmaxf(v10, 0.f); v11 = fmaxf(v11, 0.f);
            }
            if (osplit) {
                // (row0,col) and (row0+8,col) are adjacent slots -> float2 stores
                float h00 = tf32r(v00), l00 = tf32r(v00 - h00);
                float h01 = tf32r(v01), l01 = tf32r(v01 - h01);
                float h10 = tf32r(v10), l10 = tf32r(v10 - h10);
                float h11 = tf32r(v11), l11 = tf32r(v11 - h11);
                int d0 = fragdst(row0, col, oKs);       // slot even; +1 = row0+8
                *(float2*)(O1 + d0)     = make_float2(h00, h10);
                *(float2*)(O2 + d0)     = make_float2(l00, l10);
                *(float2*)(O1 + d0 + 4) = make_float2(h01, h11);
                *(float2*)(O2 + d0 + 4) = make_float2(l01, l11);
            } else {
                int sgi = col / seg;
                float* Cp = (sgi == 0) ? C0 : ((sgi == 1) ? C1 : C2);
                int ccc = col - sgi * seg;
                *(float2*)(Cp + (size_t)row0 * seg + ccc) = make_float2(v00, v01);
                *(float2*)(Cp + (size_t)(row0 + 8) * seg + ccc) = make_float2(v10, v11);
            }
        }
    }
}

// ---------------- attention over cached K/V (writes split output) ----------------
__global__ void k_attn(int l, int npos) {
    int n = blockIdx.x;
    int col = threadIdx.x;
    float q = g_qbuf[(size_t)n * DM + col];
    float s[4];
    float m = -1e30f;
    #pragma unroll
    for (int j = 0; j < 4; j++) {
        if (j < npos) {
            float kv = g_kc[((size_t)(l * NSTEP + j) * NR + n) * DM + col];
            float prod = q * kv;
            #pragma unroll
            for (int o = 16; o > 0; o >>= 1) prod += __shfl_xor_sync(0xffffffffu, prod, o);
            s[j] = prod / sqrtf(32.f);
            m = fmaxf(m, s[j]);
        }
    }
    float den = 0.f, o = 0.f;
    #pragma unroll
    for (int j = 0; j < 4; j++) {
        if (j < npos) {
            float p = expf(s[j] - m);
            den += p;
            o += p * g_vc[((size_t)(l * NSTEP + j) * NR + n) * DM + col];
        }
    }
    store_split(g_aA1, g_aA2, n, col, 32, o / den);
}

// ---------------- residual + layernorm (writes h + splits); dorot block0 resets g_mm ----
__global__ void k_ln(const float* __restrict__ delta, const float* __restrict__ gg,
                     const float* __restrict__ bb, int dorot, int pos) {
    if (dorot && blockIdx.x == 0 && threadIdx.x == 0) { g_mm[0] = 0xFFFFFFFFu; g_mm[1] = 0u; }
    int warp = threadIdx.x >> 5, lane = threadIdx.x & 31;
    int n = blockIdx.x * 8 + warp;
    float v[8];
    float sum = 0.f;
    #pragma unroll
    for (int k = 0; k < 8; k++) {
        int c = k * 32 + lane;
        v[k] = g_h[(size_t)n * DM + c] + delta[(size_t)n * DM + c];
        sum += v[k];
    }
    #pragma unroll
    for (int o = 16; o > 0; o >>= 1) sum += __shfl_xor_sync(0xffffffffu, sum, o);
    float mu = sum / 256.f;
    float var = 0.f;
    #pragma unroll
    for (int k = 0; k < 8; k++) { float d = v[k] - mu; var += d * d; }
    #pragma unroll
    for (int o = 16; o > 0; o >>= 1) var += __shfl_xor_sync(0xffffffffu, var, o);
    var /= 256.f;
    float inv = 1.f / sqrtf(var + 1e-5f);
    #pragma unroll
    for (int k = 0; k < 8; k++) {
        int c = k * 32 + lane;
        float out = (v[k] - mu) * inv * gg[c] + bb[c];
        g_h[(size_t)n * DM + c] = out;
        store_split(g_hA1, g_hA2, n, c, 32, out);
        if (dorot) {
            float p = __shfl_xor_sync(0xffffffffu, out, 1);
            float2 cs = g_ropetab[pos * 128 + (c >> 1)];
            float sgn = (c & 1) ? 1.f : -1.f;
            float vr = out * cs.x + sgn * p * cs.y;
            store_split(g_rA1, g_rA2, n, c, 32, vr);
        }
    }
}

// ---------------- out projection (N x 9) + fused block min/max of z_pred ----------------
__global__ void k_outproj(const float* __restrict__ out_w, const float* __restrict__ out_b) {
    __shared__ unsigned szn[8], szx[8];
    int warp = threadIdx.x >> 5, lane = threadIdx.x & 31;
    int n = blockIdx.x * 8 + warp;
    float hv[8];
    #pragma unroll
    for (int k = 0; k < 8; k++) hv[k] = g_h[(size_t)n * DM + k * 32 + lane];
    #pragma unroll
    for (int j = 0; j < 9; j++) {
        float acc = 0.f;
        #pragma unroll
        for (int k = 0; k < 8; k++) acc += hv[k] * out_w[j * DM + k * 32 + lane];
        #pragma unroll
        for (int o = 16; o > 0; o >>= 1) acc += __shfl_xor_sync(0xffffffffu, acc, o);
        if (lane == 0) {
            g_z[n * 9 + j] = acc + out_b[j];
            if (j == 0) { unsigned e = f2u(acc + out_b[0]); szn[warp] = e; szx[warp] = e; }
        }
    }
    __syncthreads();
    if (threadIdx.x == 0) {
        unsigned mn = szn[0], mx = szx[0];
        #pragma unroll
        for (int w = 1; w < 8; w++) {
            mn = (szn[w] < mn) ? szn[w] : mn;
            mx = (szx[w] > mx) ? szx[w] : mx;
        }
        atomicMin(&g_mm[0], mn);
        atomicMax(&g_mm[1], mx);
    }
}

// ---------------- bin assignment (also clears histograms for k_hist) ----------------
__global__ void k_bins(int step) {
    int n = blockIdx.x * blockDim.x + threadIdx.x;
    g_Hc[n] = 0.f;                 // VOC*KL == NR exactly
    if (n < VOC) g_Hm1[n] = 0.f;
    float MN = u2f(g_mm[0]);
    float MX = u2f(g_mm[1]);
    float x = g_z[n * 9];
    float bb[7];
    #pragma unroll
    for (int j = 0; j < 7; j++) bb[j] = g_z[n * 9 + 1 + j];
    int bin = -1;
    float xq = 0.f;
    #pragma unroll
    for (int j = 0; j < 8; j++) {
        float l = (j == 0) ? MN - 0.01f : bb[j - 1];
        float r = (j == 7) ? MX + 0.01f : bb[j];
        if (bin < 0 && x >= l && x < r && r > l) { bin = j; xq = (l + r) * 0.5f; }
    }
    g_bin[n] = bin;
    g_zarr[step * NR + n] = x;
    g_qarr[step * NR + n] = xq;
}

// ---------------- histogram ----------------
__global__ void k_hist() {
    int n = blockIdx.x * 256 + threadIdx.x;
    int g = g_gid[n];
    if (g < 0 || g >= VOC) return;
    int bin = g_bin[n];
    if (bin >= 0) atomicAdd(&g_Hc[g * KL + bin], 1.f);
    else atomicAdd(&g_Hm1[g], 1.f);
}

// ---------------- ratios update ----------------
__global__ void k_ratupd() {
    int v = blockIdx.x * 256 + threadIdx.x;
    #pragma unroll
    for (int k = 0; k < 7; k++) {
        float hc = g_Hc[v * KL + k];
        if (hc > 0.f) g_rat[v * KL + k] = hc;
    }
    float hc7 = g_Hc[v * KL + 7], hm = g_Hm1[v], old7 = g_rat[v * KL + 7];
    g_rat[v * KL + 7] = hc7 > 0.f ? hc7 : (hm > 0.f ? hm : old7);
}

// ---------------- grad dot + order clip ----------------
__global__ void __launch_bounds__(256) k_grad(int step) {
    __shared__ float sd[256], sc[256];
    int t = threadIdx.x;
    int n = blockIdx.x * 256 + t;
    int g = g_gid[n];
    g = g < 0 ? 0 : (g > VOC - 1 ? VOC - 1 : g);
    float r[8];
    #pragma unroll
    for (int k = 0; k < 8; k++) r[k] = g_rat[g * KL + k];
    float gr[7];
    float nrm = 0.f;
    #pragma unroll
    for (int k = 0; k < 7; k++) { gr[k] = -(r[k + 1] - r[k]); nrm += gr[k] * gr[k]; }
    nrm = sqrtf(nrm);
    float bby[7];
    #pragma unroll
    for (int k = 0; k < 7; k++) bby[k] = g_z[n * 9 + 1 + k];
    float dot = 0.f;
    #pragma unroll
    for (int k = 0; k < 7; k++) dot += bby[k] * (gr[k] / nrm);
    float cl = 0.f;
    #pragma unroll
    for (int k = 0; k < 6; k++) {
        float d = bby[k + 1] - bby[k];
        d = fmaxf(d, -9999999.f);
        d = fminf(d, 0.1f);
        cl += d;
    }
    int bin = g_bin[n];
    g_gid[n] += bin * (1 << (3 * step));
    g_code[n] = (float)bin;
    sd[t] = dot; sc[t] = cl;
    __syncthreads();
    for (int s = 128; s > 0; s >>= 1) {
        if (t < s) { sd[t] += sd[t + s]; sc[t] += sc[t + s]; }
        __syncthreads();
    }
    if (t == 0) { g_pdot[blockIdx.x] = sd[0]; g_pclip[blockIdx.x] = sc[0]; }
}

__global__ void k_losses() {
    __shared__ float sd[128], sc[128];
    int t = threadIdx.x;
    sd[t] = g_pdot[t]; sc[t] = g_pclip[t];
    __syncthreads();
    for (int s = 64; s > 0; s >>= 1) {
        if (t < s) { sd[t] += sd[t + s]; sc[t] += sc[t + s]; }
        __syncthreads();
    }
    if (t == 0) g_uni += sd[0] / (float)NR - sc[0] / ((float)NR * 6.f);
}

// ---------------- vq loss partials ----------------
__global__ void k_vqpart() {
    __shared__ float s[256];
    int t = threadIdx.x;
    int n = blockIdx.x * 256 + t;
    float acc = 0.f;
    #pragma unroll
    for (int j = 0; j < NSTEP; j++) {
        float d = g_qarr[j * NR + n] - g_zarr[j * NR + n];
        acc += d * d;
    }
    s[t] = acc;
    __syncthreads();
    for (int r = 128; r > 0; r >>= 1) {
        if (t < r) s[t] += s[t + r];
        __syncthreads();
    }
    if (t == 0) g_pvq[blockIdx.x] = s[0];
}

// ---------------- final projection ----------------
__global__ void k_zq(const float* __restrict__ ppw, const float* __restrict__ ppb,
                     float* __restrict__ out) {
    int t = blockIdx.x * blockDim.x + threadIdx.x;
    int b = t >> 15;
    int rem = t & 32767;
    int cz = rem >> 10;
    int l = rem & 1023;
    int n = (b << 10) + l;
    float acc = ppb[cz];
    #pragma unroll
    for (int j = 0; j < 4; j++) {
        float q = g_qarr[j * NR + n], z = g_zarr[j * NR + n];
        float s = (q + z) - z;
        acc += s * ppw[cz * 4 + j];
    }
    out[t] = acc;
}

__global__ void k_scalars(float* __restrict__ out, int out_size) {
    __shared__ float s[128];
    int t = threadIdx.x;
    s[t] = g_pvq[t];
    __syncthreads();
    for (int r = 64; r > 0; r >>= 1) {
        if (t < r) s[t] += s[t + r];
        __syncthreads();
    }
    if (t == 0) {
        out[out_size - 2] = s[0] / (float)(NR * NSTEP);
        out[out_size - 1] = g_uni;
    }
}

// ---------------- host ----------------
static void gemm_mma(const float* ah1, const float* ah2, const float* ar1, const float* ar2,
                     const float* w1, const float* w2, const float* bias,
                     float* C0, float* C1, float* C2, int seg,
                     int N, int K, int relu, int ropeN,
                     int osplit, float* O1, float* O2, int oKs) {
    dim3 grid(N / 64, NR / 128);
    k_gemm_mma<<<grid, 256, SMEM_MMA>>>(ah1, ah2, ar1, ar2, w1, w2, bias,
                                        C0, C1, C2, seg, N, K, relu, ropeN,
                                        osplit, O1, O2, oKs);
}

extern "C" void kernel_launch(void* const* d_in, const int* in_sizes, int n_in,
                              void* d_out, int out_size) {
    const float* x     = (const float*)d_in[0];
    const float* ppvw  = (const float*)d_in[1];
    const float* ppvb  = (const float*)d_in[2];
    const float* ppow  = (const float*)d_in[3];
    const float* ppob  = (const float*)d_in[4];
    const float* in_w  = (const float*)d_in[5];
    const float* in_b  = (const float*)d_in[6];
    const float* out_w = (const float*)d_in[7];
    const float* out_b = (const float*)d_in[8];
    const float* qkv_w = (const float*)d_in[9];
    const float* qkv_b = (const float*)d_in[10];
    const float* ao_w  = (const float*)d_in[11];
    const float* ao_b  = (const float*)d_in[12];
    const float* f1_w  = (const float*)d_in[13];
    const float* f1_b  = (const float*)d_in[14];
    const float* f2_w  = (const float*)d_in[15];
    const float* f2_b  = (const float*)d_in[16];
    const float* ln1g  = (const float*)d_in[17];
    const float* ln1b  = (const float*)d_in[18];
    const float* ln2g  = (const float*)d_in[19];
    const float* ln2b  = (const float*)d_in[20];
    const float* rat0  = (const float*)d_in[21];
    float* out = (float*)d_out;

    cudaFuncSetAttribute(k_gemm_mma, cudaFuncAttributeMaxDynamicSharedMemorySize, SMEM_MMA);

    float *h, *qb, *d1, *kc, *vc, *w1, *w2;
    float *hA1, *hA2, *rA1, *rA2, *aA1, *aA2, *dA1, *dA2;
    cudaGetSymbolAddress((void**)&h,   g_h);
    cudaGetSymbolAddress((void**)&qb,  g_qbuf);
    cudaGetSymbolAddress((void**)&d1,  g_d1);
    cudaGetSymbolAddress((void**)&kc,  g_kc);
    cudaGetSymbolAddress((void**)&vc,  g_vc);
    cudaGetSymbolAddress((void**)&w1,  g_w1);
    cudaGetSymbolAddress((void**)&w2,  g_w2);
    cudaGetSymbolAddress((void**)&hA1, g_hA1);
    cudaGetSymbolAddress((void**)&hA2, g_hA2);
    cudaGetSymbolAddress((void**)&rA1, g_rA1);
    cudaGetSymbolAddress((void**)&rA2, g_rA2);
    cudaGetSymbolAddress((void**)&aA1, g_aA1);
    cudaGetSymbolAddress((void**)&aA2, g_aA2);
    cudaGetSymbolAddress((void**)&dA1, g_dA1);
    cudaGetSymbolAddress((void**)&dA2, g_dA2);

    k_init<<<NR / 256, 256>>>(x, ppvw, ppvb, rat0);
    for (int l = 0; l < NLAY; l++) {
        k_splitw2<<<(768 * DM) / 256, 256>>>(qkv_w + (size_t)l * 768 * DM,
                                             w1 + OFF_QKV + (size_t)l * 768 * DM,
                                             w2 + OFF_QKV + (size_t)l * 768 * DM, 768, DM);
        k_splitw2<<<(DM * DM) / 256, 256>>>(ao_w + (size_t)l * DM * DM,
                                            w1 + OFF_AO + (size_t)l * DM * DM,
                                            w2 + OFF_AO + (size_t)l * DM * DM, DM, DM);
        k_splitw2<<<(FFD * DM) / 256, 256>>>(f1_w + (size_t)l * FFD * DM,
                                             w1 + OFF_F1 + (size_t)l * FFD * DM,
                                             w2 + OFF_F1 + (size_t)l * FFD * DM, FFD, DM);
        k_splitw2<<<(DM * FFD) / 256, 256>>>(f2_w + (size_t)l * DM * FFD,
                                             w1 + OFF_F2 + (size_t)l * DM * FFD,
                                             w2 + OFF_F2 + (size_t)l * DM * FFD, DM, FFD);
    }

    for (int i = 0; i < NSTEP; i++) {
        k_embed<<<NR * DM / 256, 256>>>(in_w, in_b, i);
        for (int l = 0; l < NLAY; l++) {
            const float* bl = qkv_b + l * 768;
            float* kslot = kc + (size_t)(l * NSTEP + i) * NR * DM;
            float* vslot = vc + (size_t)(l * NSTEP + i) * NR * DM;
            size_t oq = OFF_QKV + (size_t)l * 768 * DM;
            gemm_mma(hA1, hA2, rA1, rA2, w1 + oq, w2 + oq, bl,
                     qb, kslot, vslot, 256, 768, DM, 0, 512, 0, nullptr, nullptr, 0);
            k_attn<<<NR, 256>>>(l, i + 1);
            size_t oa = OFF_AO + (size_t)l * DM * DM;
            gemm_mma(aA1, aA2, aA1, aA2, w1 + oa, w2 + oa, ao_b + l * DM,
                     d1, nullptr, nullptr, DM, DM, DM, 0, 0, 0, nullptr, nullptr, 0);
            k_ln<<<NR / 8, 256>>>(d1, ln1g + l * DM, ln1b + l * DM, 0, i);
            size_t of1 = OFF_F1 + (size_t)l * FFD * DM;
            gemm_mma(hA1, hA2, hA1, hA2, w1 + of1, w2 + of1, f1_b + l * FFD,
                     nullptr, nullptr, nullptr, FFD, FFD, DM, 1, 0, 1, dA1, dA2, 64);
            size_t of2 = OFF_F2 + (size_t)l * DM * FFD;
            gemm_mma(dA1, dA2, dA1, dA2, w1 + of2, w2 + of2, f2_b + l * DM,
                     d1, nullptr, nullptr, DM, DM, FFD, 0, 0, 0, nullptr, nullptr, 0);
            k_ln<<<NR / 8, 256>>>(d1, ln2g + l * DM, ln2b + l * DM, 1, i);
        }
        k_outproj<<<NR / 8, 256>>>(out_w, out_b);
        k_bins<<<NR / 256, 256>>>(i);
        k_hist<<<NR / 256, 256>>>();
        k_ratupd<<<VOC / 256, 256>>>();
        k_grad<<<128, 256>>>(i);
        k_losses<<<1, 128>>>();
    }

    k_vqpart<<<128, 256>>>();
    k_zq<<<(NR * 32) / 256, 256>>>(ppow, ppob, out);
    k_scalars<<<1, 128>>>(out, out_size);
}

// round 16
// speedup vs baseline: 1.1011x; 1.1011x over previous
#include <cuda_runtime.h>
#include <math.h>
#include <stdint.h>

#define NR 32768
#define DM 256
#define NLAY 3
#define NSTEP 4
#define FFD 512
#define VOC 4096
#define KL 8

// weight split region offsets (floats)
#define OFF_QKV 0
#define OFF_AO  589824
#define OFF_F1  786432
#define OFF_F2  1179648
#define W_TOTAL 1572864

// smem: 2 buffers x (A1 4096 | A2 4096 | B1 2048 | B2 2048) floats
#define SMEM_MMA (2 * 12288 * 4)   // 98304 bytes

// ---------------- persistent device scratch ----------------
__device__ float g_xt[NR * 4];
__device__ float g_code[NR];
__device__ int   g_gid[NR];
__device__ int   g_bin[NR];
__device__ float g_h[NR * DM];
__device__ float g_qbuf[NR * DM];
__device__ float g_d1[NR * DM];
__device__ float g_kc[NLAY * NSTEP * NR * DM];
__device__ float g_vc[NLAY * NSTEP * NR * DM];
__device__ float g_w1[W_TOTAL];
__device__ float g_w2[W_TOTAL];
// fragment-ordered tf32 split activation buffers
__device__ float g_hA1[NR * DM];
__device__ float g_hA2[NR * DM];
__device__ float g_rA1[NR * DM];
__device__ float g_rA2[NR * DM];
__device__ float g_aA1[NR * DM];
__device__ float g_aA2[NR * DM];
__device__ float g_dA1[NR * FFD];
__device__ float g_dA2[NR * FFD];
__device__ float g_z[NR * 9];
__device__ float g_zarr[NSTEP * NR];
__device__ float g_qarr[NSTEP * NR];
__device__ float g_Hc[VOC * KL];
__device__ float g_Hm1[VOC];
__device__ float g_rat[VOC * KL];
__device__ float2 g_ropetab[NSTEP * 128];
__device__ unsigned g_mm[2];
__device__ float g_pdot[128];
__device__ float g_pclip[128];
__device__ float g_pvq[128];
__device__ float g_uni;

// ---------------- helpers ----------------
__device__ __forceinline__ unsigned f2u(float f) {
    unsigned u = __float_as_uint(f);
    return (u & 0x80000000u) ? ~u : (u | 0x80000000u);
}
__device__ __forceinline__ float u2f(unsigned u) {
    u = (u & 0x80000000u) ? (u & 0x7fffffffu) : ~u;
    return __uint_as_float(u);
}
__device__ __forceinline__ float tf32r(float a) {
    uint32_t u;
    asm("cvt.rna.tf32.f32 %0, %1;" : "=r"(u) : "f"(a));
    return __uint_as_float(u);
}
__device__ __forceinline__ void mma8(float* d, const uint32_t* a, const uint32_t* b) {
    asm volatile(
        "mma.sync.aligned.m16n8k8.row.col.f32.tf32.tf32.f32 "
        "{%0,%1,%2,%3}, {%4,%5,%6,%7}, {%8,%9}, {%0,%1,%2,%3};"
        : "+f"(d[0]), "+f"(d[1]), "+f"(d[2]), "+f"(d[3])
        : "r"(a[0]), "r"(a[1]), "r"(a[2]), "r"(a[3]), "r"(b[0]), "r"(b[1]));
}
__device__ __forceinline__ void cpa16(uint32_t dst, const void* src) {
    asm volatile("cp.async.cg.shared.global [%0], [%1], 16;" :: "r"(dst), "l"(src) : "memory");
}
// fragment slot for A element (m,k) with consumer K/8 == Ks (4 floats per lane: a0,a1,a2,a3)
__device__ __forceinline__ int fragdst(int m, int k, int Ks) {
    return (((m >> 4) * Ks + (k >> 3)) << 7)
         + (((m & 7) * 4 + (k & 3)) << 2)
         + ((m >> 3) & 1) + (((k >> 2) & 1) << 1);
}
__device__ __forceinline__ void store_split(float* d1, float* d2, int m, int k, int Ks, float v) {
    float hi = tf32r(v);
    float lo = tf32r(v - hi);
    int dst = fragdst(m, k, Ks);
    d1[dst] = hi;
    d2[dst] = lo;
}

// ---------------- init ----------------
__global__ void k_init(const float* __restrict__ x, const float* __restrict__ pw,
                       const float* __restrict__ pb, const float* __restrict__ rat0) {
    int n = blockIdx.x * blockDim.x + threadIdx.x;
    if (n < NR) {
        int b = n >> 10, l = n & 1023;
        const float* xb = x + (size_t)b * 32768 + l;
        #pragma unroll
        for (int j = 0; j < 4; j++) {
            float acc = pb[j];
            #pragma unroll
            for (int cz = 0; cz < 32; cz++) acc += xb[cz * 1024] * pw[j * 32 + cz];
            g_xt[n * 4 + j] = tanhf(acc);
        }
        g_code[n] = 0.f;
        g_gid[n] = 0;
    }
    if (n < VOC * KL) g_rat[n] = rat0[n];
    if (n < NSTEP * 128) {
        int pos = n >> 7, j = n & 127;
        float inv = powf(10000.f, -(float)(2 * j) / 256.f);
        float ang = (float)pos * inv;
        g_ropetab[n] = make_float2(cosf(ang), sinf(ang));
    }
    if (n == 0) g_uni = 0.f;
}

// ---------------- weight split into tf32 hi/lo, MMA-FRAGMENT order (B side) ----------------
__global__ void k_splitw2(const float* __restrict__ src, float* __restrict__ d1,
                          float* __restrict__ d2, int Nn, int Kk) {
    int i = blockIdx.x * 256 + threadIdx.x;
    if (i >= Nn * Kk) return;
    int n = i / Kk, k = i % Kk;
    float v = src[i];
    float w1 = tf32r(v);
    float w2 = tf32r(v - w1);
    int dst = (((n >> 3) * (Kk >> 3) + (k >> 3)) * 64) + ((n & 7) * 4 + ((k & 7) & 3)) * 2 + ((k & 7) >> 2);
    d1[dst] = w1;
    d2[dst] = w2;
}

// ---------------- embed: h linear + plain split + rope split ----------------
__global__ void k_embed(const float* __restrict__ in_w, const float* __restrict__ in_b, int step) {
    int idx = blockIdx.x * blockDim.x + threadIdx.x;
    int n = idx >> 8, d = idx & 255;
    float v = g_code[n] * in_w[2 * d] + g_xt[n * 4 + step] * in_w[2 * d + 1] + in_b[d];
    g_h[idx] = v;
    store_split(g_hA1, g_hA2, n, d, 32, v);
    float p = __shfl_xor_sync(0xffffffffu, v, 1);
    float2 cs = g_ropetab[step * 128 + (d >> 1)];
    float sgn = (d & 1) ? 1.f : -1.f;
    float vr = v * cs.x + sgn * p * cs.y;
    store_split(g_rA1, g_rA2, n, d, 32, vr);
}

// ---------------- pure cp.async + mma GEMM (3-term dual-acc, frag-ordered operands) ----
// C[M,N] = A[M,K] @ W[N,K]^T + bias; CTA tile 128x64, 256 threads,
// warp grid 4(M)x2(N), warp tile 32x32 via m16n8k8.
// Single __syncthreads per chunk: wait -> sync -> issue(c+1) -> mma(c).
__global__ void __launch_bounds__(256, 2) k_gemm_mma(
    const float* __restrict__ Ah1, const float* __restrict__ Ah2,
    const float* __restrict__ Ar1, const float* __restrict__ Ar2,
    const float* __restrict__ W1, const float* __restrict__ W2,
    const float* __restrict__ bias,
    float* __restrict__ C0, float* __restrict__ C1, float* __restrict__ C2,
    int seg, int N, int K, int relu, int ropeN,
    int osplit, float* __restrict__ O1, float* __restrict__ O2, int oKs) {
    extern __shared__ float smf[];
    const int tid = threadIdx.x;
    const int bm = blockIdx.y * 128;
    const int bn = blockIdx.x * 64;
    const float* A1g = (bn < ropeN) ? Ar1 : Ah1;
    const float* A2g = (bn < ropeN) ? Ar2 : Ah2;
    const int warp = tid >> 5, lane = tid & 31;
    const int rr = lane >> 2, cc = lane & 3;
    const int Ks = K >> 3;
    const int nC = K >> 5;
    const int wnb = (warp >> 2) * 4;
    const int abg0 = bm >> 4;
    const int nbg0 = bn >> 3;

    float accH[2][4][4], accC[2][4][4];
    #pragma unroll
    for (int mt = 0; mt < 2; mt++)
        #pragma unroll
        for (int nt = 0; nt < 4; nt++)
            #pragma unroll
            for (int q = 0; q < 4; q++) { accH[mt][nt][q] = 0.f; accC[mt][nt][q] = 0.f; }

    // prologue: issue chunk 0 into buffer 0
    {
        float* A1p = smf;
        #pragma unroll
        for (int i = 0; i < 4; i++) {
            int f4 = tid + i * 256;
            int ab = f4 >> 7, rem = f4 & 127;
            size_t src = ((size_t)(abg0 + ab) * Ks) * 128 + rem * 4;
            cpa16((uint32_t)__cvta_generic_to_shared(A1p + f4 * 4), A1g + src);
            cpa16((uint32_t)__cvta_generic_to_shared(A1p + 4096 + f4 * 4), A2g + src);
        }
        #pragma unroll
        for (int i = 0; i < 2; i++) {
            int f4 = tid + i * 256;
            int nb = f4 >> 6, rem = f4 & 63;
            size_t src = ((size_t)(nbg0 + nb) * Ks) * 64 + rem * 4;
            cpa16((uint32_t)__cvta_generic_to_shared(A1p + 8192 + f4 * 4), W1 + src);
            cpa16((uint32_t)__cvta_generic_to_shared(A1p + 10240 + f4 * 4), W2 + src);
        }
        asm volatile("cp.async.commit_group;" ::: "memory");
    }

    for (int c = 0; c < nC; c++) {
        const int buf = c & 1;
        float* A1p = smf + buf * 12288;
        float* A2p = A1p + 4096;
        float* B1p = A1p + 8192;
        float* B2p = A1p + 10240;

        asm volatile("cp.async.wait_group 0;" ::: "memory");
        __syncthreads();   // also proves all warps finished mma(c-1) on buf^1

        if (c + 1 < nC) {
            float* nA1 = smf + (buf ^ 1) * 12288;
            int sg0 = (c + 1) * 4;
            #pragma unroll
            for (int i = 0; i < 4; i++) {
                int f4 = tid + i * 256;
                int ab = f4 >> 7, rem = f4 & 127;
                size_t src = ((size_t)(abg0 + ab) * Ks + sg0) * 128 + rem * 4;
                cpa16((uint32_t)__cvta_generic_to_shared(nA1 + f4 * 4), A1g + src);
                cpa16((uint32_t)__cvta_generic_to_shared(nA1 + 4096 + f4 * 4), A2g + src);
            }
            #pragma unroll
            for (int i = 0; i < 2; i++) {
                int f4 = tid + i * 256;
                int nb = f4 >> 6, rem = f4 & 63;
                size_t src = ((size_t)(nbg0 + nb) * Ks + sg0) * 64 + rem * 4;
                cpa16((uint32_t)__cvta_generic_to_shared(nA1 + 8192 + f4 * 4), W1 + src);
                cpa16((uint32_t)__cvta_generic_to_shared(nA1 + 10240 + f4 * 4), W2 + src);
            }
            asm volatile("cp.async.commit_group;" ::: "memory");
        }

        #pragma unroll
        for (int s = 0; s < 4; s++) {
            uint32_t bf1[4][2], bf2[4][2];
            #pragma unroll
            for (int nt = 0; nt < 4; nt++) {
                int ob = (((wnb + nt) * 4 + s) * 32 + lane) * 2;
                float2 t1 = *(float2*)(B1p + ob);
                float2 t2 = *(float2*)(B2p + ob);
                bf1[nt][0] = __float_as_uint(t1.x); bf1[nt][1] = __float_as_uint(t1.y);
                bf2[nt][0] = __float_as_uint(t2.x); bf2[nt][1] = __float_as_uint(t2.y);
            }
            #pragma unroll
            for (int mt = 0; mt < 2; mt++) {
                int mb = (warp & 3) * 2 + mt;
                int oa = ((mb * 4 + s) * 32 + lane) * 4;
                float4 f1 = *(float4*)(A1p + oa);
                uint32_t af1[4] = {__float_as_uint(f1.x), __float_as_uint(f1.y),
                                   __float_as_uint(f1.z), __float_as_uint(f1.w)};
                #pragma unroll
                for (int nt = 0; nt < 4; nt++) mma8(accH[mt][nt], af1, bf1[nt]);
                #pragma unroll
                for (int nt = 0; nt < 4; nt++) mma8(accC[mt][nt], af1, bf2[nt]);
            }
            #pragma unroll
            for (int mt = 0; mt < 2; mt++) {
                int mb = (warp & 3) * 2 + mt;
                int oa = ((mb * 4 + s) * 32 + lane) * 4;
                float4 f2v = *(float4*)(A2p + oa);
                uint32_t af2[4] = {__float_as_uint(f2v.x), __float_as_uint(f2v.y),
                                   __float_as_uint(f2v.z), __float_as_uint(f2v.w)};
                #pragma unroll
                for (int nt = 0; nt < 4; nt++) mma8(accC[mt][nt], af2, bf1[nt]);
            }
        }
    }

    // epilogue: out = accH + accC + bias
    #pragma unroll
    for (int mt = 0; mt < 2; mt++) {
        int row0 = bm + (warp & 3) * 32 + mt * 16 + rr;
        #pragma unroll
        for (int nt = 0; nt < 4; nt++) {
            int col = bn + (warp >> 2) * 32 + nt * 8 + 2 * cc;
            float bx = bias[col], by = bias[col + 1];
            float v00 = accH[mt][nt][0] + accC[mt][nt][0] + bx;
            float v01 = accH[mt][nt][1] + accC[mt][nt][1] + by;
            float v10 = accH[mt][nt][2] + accC[mt][nt][2] + bx;
            float v11 = accH[mt][nt][3] + accC[mt][nt][3] + by;
            if (relu) {
                v00 = fmaxf(v00, 0.f); v01 = fmaxf(v01, 0.f);
                v10 = fmaxf(v10, 0.f); v11 = fmaxf(v11, 0.f);
            }
            if (osplit) {
                // (row0,col) and (row0+8,col) are adjacent slots -> float2 stores
                float h00 = tf32r(v00), l00 = tf32r(v00 - h00);
                float h01 = tf32r(v01), l01 = tf32r(v01 - h01);
                float h10 = tf32r(v10), l10 = tf32r(v10 - h10);
                float h11 = tf32r(v11), l11 = tf32r(v11 - h11);
                int d0 = fragdst(row0, col, oKs);       // slot even; +1 = row0+8
                *(float2*)(O1 + d0)     = make_float2(h00, h10);
                *(float2*)(O2 + d0)     = make_float2(l00, l10);
                *(float2*)(O1 + d0 + 4) = make_float2(h01, h11);
                *(float2*)(O2 + d0 + 4) = make_float2(l01, l11);
            } else {
                int sgi = col / seg;
                float* Cp = (sgi == 0) ? C0 : ((sgi == 1) ? C1 : C2);
                int ccc = col - sgi * seg;
                *(float2*)(Cp + (size_t)row0 * seg + ccc) = make_float2(v00, v01);
                *(float2*)(Cp + (size_t)(row0 + 8) * seg + ccc) = make_float2(v10, v11);
            }
        }
    }
}

// ---------------- attention over cached K/V (writes split output) ----------------
__global__ void k_attn(int l, int npos) {
    int n = blockIdx.x;
    int col = threadIdx.x;
    float q = g_qbuf[(size_t)n * DM + col];
    float s[4];
    float m = -1e30f;
    #pragma unroll
    for (int j = 0; j < 4; j++) {
        if (j < npos) {
            float kv = g_kc[((size_t)(l * NSTEP + j) * NR + n) * DM + col];
            float prod = q * kv;
            #pragma unroll
            for (int o = 16; o > 0; o >>= 1) prod += __shfl_xor_sync(0xffffffffu, prod, o);
            s[j] = prod / sqrtf(32.f);
            m = fmaxf(m, s[j]);
        }
    }
    float den = 0.f, o = 0.f;
    #pragma unroll
    for (int j = 0; j < 4; j++) {
        if (j < npos) {
            float p = expf(s[j] - m);
            den += p;
            o += p * g_vc[((size_t)(l * NSTEP + j) * NR + n) * DM + col];
        }
    }
    store_split(g_aA1, g_aA2, n, col, 32, o / den);
}

// ---------------- residual + layernorm (writes h + splits); dorot block0 resets g_mm ----
__global__ void k_ln(const float* __restrict__ delta, const float* __restrict__ gg,
                     const float* __restrict__ bb, int dorot, int pos) {
    if (dorot && blockIdx.x == 0 && threadIdx.x == 0) { g_mm[0] = 0xFFFFFFFFu; g_mm[1] = 0u; }
    int warp = threadIdx.x >> 5, lane = threadIdx.x & 31;
    int n = blockIdx.x * 8 + warp;
    float v[8];
    float sum = 0.f;
    #pragma unroll
    for (int k = 0; k < 8; k++) {
        int c = k * 32 + lane;
        v[k] = g_h[(size_t)n * DM + c] + delta[(size_t)n * DM + c];
        sum += v[k];
    }
    #pragma unroll
    for (int o = 16; o > 0; o >>= 1) sum += __shfl_xor_sync(0xffffffffu, sum, o);
    float mu = sum / 256.f;
    float var = 0.f;
    #pragma unroll
    for (int k = 0; k < 8; k++) { float d = v[k] - mu; var += d * d; }
    #pragma unroll
    for (int o = 16; o > 0; o >>= 1) var += __shfl_xor_sync(0xffffffffu, var, o);
    var /= 256.f;
    float inv = 1.f / sqrtf(var + 1e-5f);
    #pragma unroll
    for (int k = 0; k < 8; k++) {
        int c = k * 32 + lane;
        float out = (v[k] - mu) * inv * gg[c] + bb[c];
        g_h[(size_t)n * DM + c] = out;
        store_split(g_hA1, g_hA2, n, c, 32, out);
        if (dorot) {
            float p = __shfl_xor_sync(0xffffffffu, out, 1);
            float2 cs = g_ropetab[pos * 128 + (c >> 1)];
            float sgn = (c & 1) ? 1.f : -1.f;
            float vr = out * cs.x + sgn * p * cs.y;
            store_split(g_rA1, g_rA2, n, c, 32, vr);
        }
    }
}

// ---------------- out projection (N x 9) + fused block min/max of z_pred ----------------
__global__ void k_outproj(const float* __restrict__ out_w, const float* __restrict__ out_b) {
    __shared__ unsigned szn[8], szx[8];
    int warp = threadIdx.x >> 5, lane = threadIdx.x & 31;
    int n = blockIdx.x * 8 + warp;
    float hv[8];
    #pragma unroll
    for (int k = 0; k < 8; k++) hv[k] = g_h[(size_t)n * DM + k * 32 + lane];
    #pragma unroll
    for (int j = 0; j < 9; j++) {
        float acc = 0.f;
        #pragma unroll
        for (int k = 0; k < 8; k++) acc += hv[k] * out_w[j * DM + k * 32 + lane];
        #pragma unroll
        for (int o = 16; o > 0; o >>= 1) acc += __shfl_xor_sync(0xffffffffu, acc, o);
        if (lane == 0) {
            g_z[n * 9 + j] = acc + out_b[j];
            if (j == 0) { unsigned e = f2u(acc + out_b[0]); szn[warp] = e; szx[warp] = e; }
        }
    }
    __syncthreads();
    if (threadIdx.x == 0) {
        unsigned mn = szn[0], mx = szx[0];
        #pragma unroll
        for (int w = 1; w < 8; w++) {
            mn = (szn[w] < mn) ? szn[w] : mn;
            mx = (szx[w] > mx) ? szx[w] : mx;
        }
        atomicMin(&g_mm[0], mn);
        atomicMax(&g_mm[1], mx);
    }
}

// ---------------- bin assignment (also clears histograms for k_hist) ----------------
__global__ void k_bins(int step) {
    int n = blockIdx.x * blockDim.x + threadIdx.x;
    g_Hc[n] = 0.f;                 // VOC*KL == NR exactly
    if (n < VOC) g_Hm1[n] = 0.f;
    float MN = u2f(g_mm[0]);
    float MX = u2f(g_mm[1]);
    float x = g_z[n * 9];
    float bb[7];
    #pragma unroll
    for (int j = 0; j < 7; j++) bb[j] = g_z[n * 9 + 1 + j];
    int bin = -1;
    float xq = 0.f;
    #pragma unroll
    for (int j = 0; j < 8; j++) {
        float l = (j == 0) ? MN - 0.01f : bb[j - 1];
        float r = (j == 7) ? MX + 0.01f : bb[j];
        if (bin < 0 && x >= l && x < r && r > l) { bin = j; xq = (l + r) * 0.5f; }
    }
    g_bin[n] = bin;
    g_zarr[step * NR + n] = x;
    g_qarr[step * NR + n] = xq;
}

// ---------------- histogram ----------------
__global__ void k_hist() {
    int n = blockIdx.x * 256 + threadIdx.x;
    int g = g_gid[n];
    if (g < 0 || g >= VOC) return;
    int bin = g_bin[n];
    if (bin >= 0) atomicAdd(&g_Hc[g * KL + bin], 1.f);
    else atomicAdd(&g_Hm1[g], 1.f);
}

// ---------------- ratios update ----------------
__global__ void k_ratupd() {
    int v = blockIdx.x * 256 + threadIdx.x;
    #pragma unroll
    for (int k = 0; k < 7; k++) {
        float hc = g_Hc[v * KL + k];
        if (hc > 0.f) g_rat[v * KL + k] = hc;
    }
    float hc7 = g_Hc[v * KL + 7], hm = g_Hm1[v], old7 = g_rat[v * KL + 7];
    g_rat[v * KL + 7] = hc7 > 0.f ? hc7 : (hm > 0.f ? hm : old7);
}

// ---------------- grad dot + order clip ----------------
__global__ void __launch_bounds__(256) k_grad(int step) {
    __shared__ float sd[256], sc[256];
    int t = threadIdx.x;
    int n = blockIdx.x * 256 + t;
    int g = g_gid[n];
    g = g < 0 ? 0 : (g > VOC - 1 ? VOC - 1 : g);
    float r[8];
    #pragma unroll
    for (int k = 0; k < 8; k++) r[k] = g_rat[g * KL + k];
    float gr[7];
    float nrm = 0.f;
    #pragma unroll
    for (int k = 0; k < 7; k++) { gr[k] = -(r[k + 1] - r[k]); nrm += gr[k] * gr[k]; }
    nrm = sqrtf(nrm);
    float bby[7];
    #pragma unroll
    for (int k = 0; k < 7; k++) bby[k] = g_z[n * 9 + 1 + k];
    float dot = 0.f;
    #pragma unroll
    for (int k = 0; k < 7; k++) dot += bby[k] * (gr[k] / nrm);
    float cl = 0.f;
    #pragma unroll
    for (int k = 0; k < 6; k++) {
        float d = bby[k + 1] - bby[k];
        d = fmaxf(d, -9999999.f);
        d = fminf(d, 0.1f);
        cl += d;
    }
    int bin = g_bin[n];
    g_gid[n] += bin * (1 << (3 * step));
    g_code[n] = (float)bin;
    sd[t] = dot; sc[t] = cl;
    __syncthreads();
    for (int s = 128; s > 0; s >>= 1) {
        if (t < s) { sd[t] += sd[t + s]; sc[t] += sc[t + s]; }
        __syncthreads();
    }
    if (t == 0) { g_pdot[blockIdx.x] = sd[0]; g_pclip[blockIdx.x] = sc[0]; }
}

__global__ void k_losses() {
    __shared__ float sd[128], sc[128];
    int t = threadIdx.x;
    sd[t] = g_pdot[t]; sc[t] = g_pclip[t];
    __syncthreads();
    for (int s = 64; s > 0; s >>= 1) {
        if (t < s) { sd[t] += sd[t + s]; sc[t] += sc[t + s]; }
        __syncthreads();
    }
    if (t == 0) g_uni += sd[0] / (float)NR - sc[0] / ((float)NR * 6.f);
}

// ---------------- vq loss partials ----------------
__global__ void k_vqpart() {
    __shared__ float s[256];
    int t = threadIdx.x;
    int n = blockIdx.x * 256 + t;
    float acc = 0.f;
    #pragma unroll
    for (int j = 0; j < NSTEP; j++) {
        float d = g_qarr[j * NR + n] - g_zarr[j * NR + n];
        acc += d * d;
    }
    s[t] = acc;
    __syncthreads();
    for (int r = 128; r > 0; r >>= 1) {
        if (t < r) s[t] += s[t + r];
        __syncthreads();
    }
    if (t == 0) g_pvq[blockIdx.x] = s[0];
}

// ---------------- final projection ----------------
__global__ void k_zq(const float* __restrict__ ppw, const float* __restrict__ ppb,
                     float* __restrict__ out) {
    int t = blockIdx.x * blockDim.x + threadIdx.x;
    int b = t >> 15;
    int rem = t & 32767;
    int cz = rem >> 10;
    int l = rem & 1023;
    int n = (b << 10) + l;
    float acc = ppb[cz];
    #pragma unroll
    for (int j = 0; j < 4; j++) {
        float q = g_qarr[j * NR + n], z = g_zarr[j * NR + n];
        float s = (q + z) - z;
        acc += s * ppw[cz * 4 + j];
    }
    out[t] = acc;
}

__global__ void k_scalars(float* __restrict__ out, int out_size) {
    __shared__ float s[128];
    int t = threadIdx.x;
    s[t] = g_pvq[t];
    __syncthreads();
    for (int r = 64; r > 0; r >>= 1) {
        if (t < r) s[t] += s[t + r];
        __syncthreads();
    }
    if (t == 0) {
        out[out_size - 2] = s[0] / (float)(NR * NSTEP);
        out[out_size - 1] = g_uni;
    }
}

// ---------------- host ----------------
static void gemm_mma(const float* ah1, const float* ah2, const float* ar1, const float* ar2,
                     const float* w1, const float* w2, const float* bias,
                     float* C0, float* C1, float* C2, int seg,
                     int N, int K, int relu, int ropeN,
                     int osplit, float* O1, float* O2, int oKs) {
    dim3 grid(N / 64, NR / 128);
    k_gemm_mma<<<grid, 256, SMEM_MMA>>>(ah1, ah2, ar1, ar2, w1, w2, bias,
                                        C0, C1, C2, seg, N, K, relu, ropeN,
                                        osplit, O1, O2, oKs);
}

extern "C" void kernel_launch(void* const* d_in, const int* in_sizes, int n_in,
                              void* d_out, int out_size) {
    const float* x     = (const float*)d_in[0];
    const float* ppvw  = (const float*)d_in[1];
    const float* ppvb  = (const float*)d_in[2];
    const float* ppow  = (const float*)d_in[3];
    const float* ppob  = (const float*)d_in[4];
    const float* in_w  = (const float*)d_in[5];
    const float* in_b  = (const float*)d_in[6];
    const float* out_w = (const float*)d_in[7];
    const float* out_b = (const float*)d_in[8];
    const float* qkv_w = (const float*)d_in[9];
    const float* qkv_b = (const float*)d_in[10];
    const float* ao_w  = (const float*)d_in[11];
    const float* ao_b  = (const float*)d_in[12];
    const float* f1_w  = (const float*)d_in[13];
    const float* f1_b  = (const float*)d_in[14];
    const float* f2_w  = (const float*)d_in[15];
    const float* f2_b  = (const float*)d_in[16];
    const float* ln1g  = (const float*)d_in[17];
    const float* ln1b  = (const float*)d_in[18];
    const float* ln2g  = (const float*)d_in[19];
    const float* ln2b  = (const float*)d_in[20];
    const float* rat0  = (const float*)d_in[21];
    float* out = (float*)d_out;

    cudaFuncSetAttribute(k_gemm_mma, cudaFuncAttributeMaxDynamicSharedMemorySize, SMEM_MMA);

    float *h, *qb, *d1, *kc, *vc, *w1, *w2;
    float *hA1, *hA2, *rA1, *rA2, *aA1, *aA2, *dA1, *dA2;
    cudaGetSymbolAddress((void**)&h,   g_h);
    cudaGetSymbolAddress((void**)&qb,  g_qbuf);
    cudaGetSymbolAddress((void**)&d1,  g_d1);
    cudaGetSymbolAddress((void**)&kc,  g_kc);
    cudaGetSymbolAddress((void**)&vc,  g_vc);
    cudaGetSymbolAddress((void**)&w1,  g_w1);
    cudaGetSymbolAddress((void**)&w2,  g_w2);
    cudaGetSymbolAddress((void**)&hA1, g_hA1);
    cudaGetSymbolAddress((void**)&hA2, g_hA2);
    cudaGetSymbolAddress((void**)&rA1, g_rA1);
    cudaGetSymbolAddress((void**)&rA2, g_rA2);
    cudaGetSymbolAddress((void**)&aA1, g_aA1);
    cudaGetSymbolAddress((void**)&aA2, g_aA2);
    cudaGetSymbolAddress((void**)&dA1, g_dA1);
    cudaGetSymbolAddress((void**)&dA2, g_dA2);

    k_init<<<NR / 256, 256>>>(x, ppvw, ppvb, rat0);
    for (int l = 0; l < NLAY; l++) {
        k_splitw2<<<(768 * DM) / 256, 256>>>(qkv_w + (size_t)l * 768 * DM,
                                             w1 + OFF_QKV + (size_t)l * 768 * DM,
                                             w2 + OFF_QKV + (size_t)l * 768 * DM, 768, DM);
        k_splitw2<<<(DM * DM) / 256, 256>>>(ao_w + (size_t)l * DM * DM,
                                            w1 + OFF_AO + (size_t)l * DM * DM,
                                            w2 + OFF_AO + (size_t)l * DM * DM, DM, DM);
        k_splitw2<<<(FFD * DM) / 256, 256>>>(f1_w + (size_t)l * FFD * DM,
                                             w1 + OFF_F1 + (size_t)l * FFD * DM,
                                             w2 + OFF_F1 + (size_t)l * FFD * DM, FFD, DM);
        k_splitw2<<<(DM * FFD) / 256, 256>>>(f2_w + (size_t)l * DM * FFD,
                                             w1 + OFF_F2 + (size_t)l * DM * FFD,
                                             w2 + OFF_F2 + (size_t)l * DM * FFD, DM, FFD);
    }

    for (int i = 0; i < NSTEP; i++) {
        k_embed<<<NR * DM / 256, 256>>>(in_w, in_b, i);
        for (int l = 0; l < NLAY; l++) {
            const float* bl = qkv_b + l * 768;
            float* kslot = kc + (size_t)(l * NSTEP + i) * NR * DM;
            float* vslot = vc + (size_t)(l * NSTEP + i) * NR * DM;
            size_t oq = OFF_QKV + (size_t)l * 768 * DM;
            gemm_mma(hA1, hA2, rA1, rA2, w1 + oq, w2 + oq, bl,
                     qb, kslot, vslot, 256, 768, DM, 0, 512, 0, nullptr, nullptr, 0);
            k_attn<<<NR, 256>>>(l, i + 1);
            size_t oa = OFF_AO + (size_t)l * DM * DM;
            gemm_mma(aA1, aA2, aA1, aA2, w1 + oa, w2 + oa, ao_b + l * DM,
                     d1, nullptr, nullptr, DM, DM, DM, 0, 0, 0, nullptr, nullptr, 0);
            k_ln<<<NR / 8, 256>>>(d1, ln1g + l * DM, ln1b + l * DM, 0, i);
            size_t of1 = OFF_F1 + (size_t)l * FFD * DM;
            gemm_mma(hA1, hA2, hA1, hA2, w1 + of1, w2 + of1, f1_b + l * FFD,
                     nullptr, nullptr, nullptr, FFD, FFD, DM, 1, 0, 1, dA1, dA2, 64);
            size_t of2 = OFF_F2 + (size_t)l * DM * FFD;
            gemm_mma(dA1, dA2, dA1, dA2, w1 + of2, w2 + of2, f2_b + l * DM,
                     d1, nullptr, nullptr, DM, DM, FFD, 0, 0, 0, nullptr, nullptr, 0);
            k_ln<<<NR / 8, 256>>>(d1, ln2g + l * DM, ln2b + l * DM, 1, i);
        }
        k_outproj<<<NR / 8, 256>>>(out_w, out_b);
        k_bins<<<NR / 256, 256>>>(i);
        k_hist<<<NR / 256, 256>>>();
        k_ratupd<<<VOC / 256, 256>>>();
        k_grad<<<128, 256>>>(i);
        k_losses<<<1, 128>>>();
    }

    k_vqpart<<<128, 256>>>();
    k_zq<<<(NR * 32) / 256, 256>>>(ppow, ppob, out);
    k_scalars<<<1, 128>>>(out, out_size);
}

// round 17
// speedup vs baseline: 1.1335x; 1.0294x over previous
#include <cuda_runtime.h>
#include <math.h>
#include <stdint.h>

#define NR 32768
#define DM 256
#define NLAY 3
#define NSTEP 4
#define FFD 512
#define VOC 4096
#define KL 8

// weight split region offsets (floats)
#define OFF_QKV 0
#define OFF_AO  589824
#define OFF_F1  786432
#define OFF_F2  1179648
#define W_TOTAL 1572864

// smem: 2 buffers x (A1 4096 | A2 4096 | B1 2048 | B2 2048) floats
#define SMEM_MMA (2 * 12288 * 4)   // 98304 bytes

// ---------------- persistent device scratch ----------------
__device__ float g_xt[NR * 4];
__device__ float g_code[NR];
__device__ int   g_gid[NR];
__device__ int   g_bin[NR];
__device__ float g_h[NR * DM];
__device__ float g_qbuf[NR * DM];
__device__ float g_d1[NR * DM];
__device__ float g_kc[NLAY * NSTEP * NR * DM];
__device__ float g_vc[NLAY * NSTEP * NR * DM];
__device__ float g_w1[W_TOTAL];
__device__ float g_w2[W_TOTAL];
// fragment-ordered tf32 split activation buffers
__device__ float g_hA1[NR * DM];
__device__ float g_hA2[NR * DM];
__device__ float g_rA1[NR * DM];
__device__ float g_rA2[NR * DM];
__device__ float g_aA1[NR * DM];
__device__ float g_aA2[NR * DM];
__device__ float g_dA1[NR * FFD];
__device__ float g_dA2[NR * FFD];
__device__ float g_z[NR * 9];
__device__ float g_zarr[NSTEP * NR];
__device__ float g_qarr[NSTEP * NR];
__device__ float g_Hc[VOC * KL];
__device__ float g_Hm1[VOC];
__device__ float g_rat[VOC * KL];
__device__ float2 g_ropetab[NSTEP * 128];
__device__ unsigned g_mm[2];
__device__ float g_pdot[128];
__device__ float g_pclip[128];
__device__ float g_pvq[128];
__device__ float g_uni;

// ---------------- helpers ----------------
__device__ __forceinline__ unsigned f2u(float f) {
    unsigned u = __float_as_uint(f);
    return (u & 0x80000000u) ? ~u : (u | 0x80000000u);
}
__device__ __forceinline__ float u2f(unsigned u) {
    u = (u & 0x80000000u) ? (u & 0x7fffffffu) : ~u;
    return __uint_as_float(u);
}
__device__ __forceinline__ float tf32r(float a) {
    uint32_t u;
    asm("cvt.rna.tf32.f32 %0, %1;" : "=r"(u) : "f"(a));
    return __uint_as_float(u);
}
__device__ __forceinline__ void mma8(float* d, const uint32_t* a, const uint32_t* b) {
    asm volatile(
        "mma.sync.aligned.m16n8k8.row.col.f32.tf32.tf32.f32 "
        "{%0,%1,%2,%3}, {%4,%5,%6,%7}, {%8,%9}, {%0,%1,%2,%3};"
        : "+f"(d[0]), "+f"(d[1]), "+f"(d[2]), "+f"(d[3])
        : "r"(a[0]), "r"(a[1]), "r"(a[2]), "r"(a[3]), "r"(b[0]), "r"(b[1]));
}
__device__ __forceinline__ void cpa16(uint32_t dst, const void* src) {
    asm volatile("cp.async.cg.shared.global [%0], [%1], 16;" :: "r"(dst), "l"(src) : "memory");
}
// fragment slot for A element (m,k) with consumer K/8 == Ks (4 floats per lane: a0,a1,a2,a3)
__device__ __forceinline__ int fragdst(int m, int k, int Ks) {
    return (((m >> 4) * Ks + (k >> 3)) << 7)
         + (((m & 7) * 4 + (k & 3)) << 2)
         + ((m >> 3) & 1) + (((k >> 2) & 1) << 1);
}
__device__ __forceinline__ void store_split(float* d1, float* d2, int m, int k, int Ks, float v) {
    float hi = tf32r(v);
    float lo = tf32r(v - hi);
    int dst = fragdst(m, k, Ks);
    d1[dst] = hi;
    d2[dst] = lo;
}

// ---------------- init ----------------
__global__ void k_init(const float* __restrict__ x, const float* __restrict__ pw,
                       const float* __restrict__ pb, const float* __restrict__ rat0) {
    int n = blockIdx.x * blockDim.x + threadIdx.x;
    if (n < NR) {
        int b = n >> 10, l = n & 1023;
        const float* xb = x + (size_t)b * 32768 + l;
        #pragma unroll
        for (int j = 0; j < 4; j++) {
            float acc = pb[j];
            #pragma unroll
            for (int cz = 0; cz < 32; cz++) acc += xb[cz * 1024] * pw[j * 32 + cz];
            g_xt[n * 4 + j] = tanhf(acc);
        }
        g_code[n] = 0.f;
        g_gid[n] = 0;
    }
    if (n < VOC * KL) g_rat[n] = rat0[n];
    if (n < NSTEP * 128) {
        int pos = n >> 7, j = n & 127;
        float inv = powf(10000.f, -(float)(2 * j) / 256.f);
        float ang = (float)pos * inv;
        g_ropetab[n] = make_float2(cosf(ang), sinf(ang));
    }
    if (n == 0) g_uni = 0.f;
}

// ---------------- weight split into tf32 hi/lo, MMA-FRAGMENT order (B side) ----------------
__global__ void k_splitw2(const float* __restrict__ src, float* __restrict__ d1,
                          float* __restrict__ d2, int Nn, int Kk) {
    int i = blockIdx.x * 256 + threadIdx.x;
    if (i >= Nn * Kk) return;
    int n = i / Kk, k = i % Kk;
    float v = src[i];
    float w1 = tf32r(v);
    float w2 = tf32r(v - w1);
    int dst = (((n >> 3) * (Kk >> 3) + (k >> 3)) * 64) + ((n & 7) * 4 + ((k & 7) & 3)) * 2 + ((k & 7) >> 2);
    d1[dst] = w1;
    d2[dst] = w2;
}

// ---------------- embed: h linear + plain split + rope split ----------------
__global__ void k_embed(const float* __restrict__ in_w, const float* __restrict__ in_b, int step) {
    int idx = blockIdx.x * blockDim.x + threadIdx.x;
    int n = idx >> 8, d = idx & 255;
    float v = g_code[n] * in_w[2 * d] + g_xt[n * 4 + step] * in_w[2 * d + 1] + in_b[d];
    g_h[idx] = v;
    store_split(g_hA1, g_hA2, n, d, 32, v);
    float p = __shfl_xor_sync(0xffffffffu, v, 1);
    float2 cs = g_ropetab[step * 128 + (d >> 1)];
    float sgn = (d & 1) ? 1.f : -1.f;
    float vr = v * cs.x + sgn * p * cs.y;
    store_split(g_rA1, g_rA2, n, d, 32, vr);
}

// ---------------- pure cp.async + mma GEMM (3-term dual-acc, frag-ordered operands) ----
// C[M,N] = A[M,K] @ W[N,K]^T + bias; CTA tile 128x64, 256 threads,
// warp grid 4(M)x2(N), warp tile 32x32 via m16n8k8.
// Single __syncthreads per chunk: wait -> sync -> issue(c+1) -> mma(c).
__global__ void __launch_bounds__(256, 2) k_gemm_mma(
    const float* __restrict__ Ah1, const float* __restrict__ Ah2,
    const float* __restrict__ Ar1, const float* __restrict__ Ar2,
    const float* __restrict__ W1, const float* __restrict__ W2,
    const float* __restrict__ bias,
    float* __restrict__ C0, float* __restrict__ C1, float* __restrict__ C2,
    int seg, int N, int K, int relu, int ropeN,
    int osplit, float* __restrict__ O1, float* __restrict__ O2, int oKs) {
    extern __shared__ float smf[];
    const int tid = threadIdx.x;
    const int bm = blockIdx.y * 128;
    const int bn = blockIdx.x * 64;
    const float* A1g = (bn < ropeN) ? Ar1 : Ah1;
    const float* A2g = (bn < ropeN) ? Ar2 : Ah2;
    const int warp = tid >> 5, lane = tid & 31;
    const int rr = lane >> 2, cc = lane & 3;
    const int Ks = K >> 3;
    const int nC = K >> 5;
    const int wnb = (warp >> 2) * 4;
    const int abg0 = bm >> 4;
    const int nbg0 = bn >> 3;

    float accH[2][4][4], accC[2][4][4];
    #pragma unroll
    for (int mt = 0; mt < 2; mt++)
        #pragma unroll
        for (int nt = 0; nt < 4; nt++)
            #pragma unroll
            for (int q = 0; q < 4; q++) { accH[mt][nt][q] = 0.f; accC[mt][nt][q] = 0.f; }

    // prologue: issue chunk 0 into buffer 0
    {
        float* A1p = smf;
        #pragma unroll
        for (int i = 0; i < 4; i++) {
            int f4 = tid + i * 256;
            int ab = f4 >> 7, rem = f4 & 127;
            size_t src = ((size_t)(abg0 + ab) * Ks) * 128 + rem * 4;
            cpa16((uint32_t)__cvta_generic_to_shared(A1p + f4 * 4), A1g + src);
            cpa16((uint32_t)__cvta_generic_to_shared(A1p + 4096 + f4 * 4), A2g + src);
        }
        #pragma unroll
        for (int i = 0; i < 2; i++) {
            int f4 = tid + i * 256;
            int nb = f4 >> 6, rem = f4 & 63;
            size_t src = ((size_t)(nbg0 + nb) * Ks) * 64 + rem * 4;
            cpa16((uint32_t)__cvta_generic_to_shared(A1p + 8192 + f4 * 4), W1 + src);
            cpa16((uint32_t)__cvta_generic_to_shared(A1p + 10240 + f4 * 4), W2 + src);
        }
        asm volatile("cp.async.commit_group;" ::: "memory");
    }

    for (int c = 0; c < nC; c++) {
        const int buf = c & 1;
        float* A1p = smf + buf * 12288;
        float* A2p = A1p + 4096;
        float* B1p = A1p + 8192;
        float* B2p = A1p + 10240;

        asm volatile("cp.async.wait_group 0;" ::: "memory");
        __syncthreads();   // also proves all warps finished mma(c-1) on buf^1

        if (c + 1 < nC) {
            float* nA1 = smf + (buf ^ 1) * 12288;
            int sg0 = (c + 1) * 4;
            #pragma unroll
            for (int i = 0; i < 4; i++) {
                int f4 = tid + i * 256;
                int ab = f4 >> 7, rem = f4 & 127;
                size_t src = ((size_t)(abg0 + ab) * Ks + sg0) * 128 + rem * 4;
                cpa16((uint32_t)__cvta_generic_to_shared(nA1 + f4 * 4), A1g + src);
                cpa16((uint32_t)__cvta_generic_to_shared(nA1 + 4096 + f4 * 4), A2g + src);
            }
            #pragma unroll
            for (int i = 0; i < 2; i++) {
                int f4 = tid + i * 256;
                int nb = f4 >> 6, rem = f4 & 63;
                size_t src = ((size_t)(nbg0 + nb) * Ks + sg0) * 64 + rem * 4;
                cpa16((uint32_t)__cvta_generic_to_shared(nA1 + 8192 + f4 * 4), W1 + src);
                cpa16((uint32_t)__cvta_generic_to_shared(nA1 + 10240 + f4 * 4), W2 + src);
            }
            asm volatile("cp.async.commit_group;" ::: "memory");
        }

        #pragma unroll
        for (int s = 0; s < 4; s++) {
            uint32_t bf1[4][2], bf2[4][2];
            #pragma unroll
            for (int nt = 0; nt < 4; nt++) {
                int ob = (((wnb + nt) * 4 + s) * 32 + lane) * 2;
                float2 t1 = *(float2*)(B1p + ob);
                float2 t2 = *(float2*)(B2p + ob);
                bf1[nt][0] = __float_as_uint(t1.x); bf1[nt][1] = __float_as_uint(t1.y);
                bf2[nt][0] = __float_as_uint(t2.x); bf2[nt][1] = __float_as_uint(t2.y);
            }
            #pragma unroll
            for (int mt = 0; mt < 2; mt++) {
                int mb = (warp & 3) * 2 + mt;
                int oa = ((mb * 4 + s) * 32 + lane) * 4;
                float4 f1 = *(float4*)(A1p + oa);
                uint32_t af1[4] = {__float_as_uint(f1.x), __float_as_uint(f1.y),
                                   __float_as_uint(f1.z), __float_as_uint(f1.w)};
                #pragma unroll
                for (int nt = 0; nt < 4; nt++) mma8(accH[mt][nt], af1, bf1[nt]);
                #pragma unroll
                for (int nt = 0; nt < 4; nt++) mma8(accC[mt][nt], af1, bf2[nt]);
            }
            #pragma unroll
            for (int mt = 0; mt < 2; mt++) {
                int mb = (warp & 3) * 2 + mt;
                int oa = ((mb * 4 + s) * 32 + lane) * 4;
                float4 f2v = *(float4*)(A2p + oa);
                uint32_t af2[4] = {__float_as_uint(f2v.x), __float_as_uint(f2v.y),
                                   __float_as_uint(f2v.z), __float_as_uint(f2v.w)};
                #pragma unroll
                for (int nt = 0; nt < 4; nt++) mma8(accC[mt][nt], af2, bf1[nt]);
            }
        }
    }

    // epilogue: out = accH + accC + bias
    #pragma unroll
    for (int mt = 0; mt < 2; mt++) {
        int row0 = bm + (warp & 3) * 32 + mt * 16 + rr;
        #pragma unroll
        for (int nt = 0; nt < 4; nt++) {
            int col = bn + (warp >> 2) * 32 + nt * 8 + 2 * cc;
            float bx = bias[col], by = bias[col + 1];
            float v00 = accH[mt][nt][0] + accC[mt][nt][0] + bx;
            float v01 = accH[mt][nt][1] + accC[mt][nt][1] + by;
            float v10 = accH[mt][nt][2] + accC[mt][nt][2] + bx;
            float v11 = accH[mt][nt][3] + accC[mt][nt][3] + by;
            if (relu) {
                v00 = fmaxf(v00, 0.f); v01 = fmaxf(v01, 0.f);
                v10 = fmaxf(v10, 0.f); v11 = fmaxf(v11, 0.f);
            }
            if (osplit) {
                // (row0,col) and (row0+8,col) are adjacent slots -> float2 stores
                float h00 = tf32r(v00), l00 = tf32r(v00 - h00);
                float h01 = tf32r(v01), l01 = tf32r(v01 - h01);
                float h10 = tf32r(v10), l10 = tf32r(v10 - h10);
                float h11 = tf32r(v11), l11 = tf32r(v11 - h11);
                int d0 = fragdst(row0, col, oKs);       // slot even; +1 = row0+8
                *(float2*)(O1 + d0)     = make_float2(h00, h10);
                *(float2*)(O2 + d0)     = make_float2(l00, l10);
                *(float2*)(O1 + d0 + 4) = make_float2(h01, h11);
                *(float2*)(O2 + d0 + 4) = make_float2(l01, l11);
            } else {
                int sgi = col / seg;
                float* Cp = (sgi == 0) ? C0 : ((sgi == 1) ? C1 : C2);
                int ccc = col - sgi * seg;
                *(float2*)(Cp + (size_t)row0 * seg + ccc) = make_float2(v00, v01);
                *(float2*)(Cp + (size_t)(row0 + 8) * seg + ccc) = make_float2(v10, v11);
            }
        }
    }
}

// ---------------- attention over cached K/V (writes split output) ----------------
// npos==1: softmax over one position is exactly 1 -> o = v (Q unused, bit-exact).
__global__ void k_attn(int l, int npos) {
    int n = blockIdx.x;
    int col = threadIdx.x;
    if (npos == 1) {
        float v = g_vc[((size_t)(l * NSTEP) * NR + n) * DM + col];
        store_split(g_aA1, g_aA2, n, col, 32, v);
        return;
    }
    float q = g_qbuf[(size_t)n * DM + col];
    float s[4];
    float m = -1e30f;
    #pragma unroll
    for (int j = 0; j < 4; j++) {
        if (j < npos) {
            float kv = g_kc[((size_t)(l * NSTEP + j) * NR + n) * DM + col];
            float prod = q * kv;
            #pragma unroll
            for (int o = 16; o > 0; o >>= 1) prod += __shfl_xor_sync(0xffffffffu, prod, o);
            s[j] = prod / sqrtf(32.f);
            m = fmaxf(m, s[j]);
        }
    }
    float den = 0.f, o = 0.f;
    #pragma unroll
    for (int j = 0; j < 4; j++) {
        if (j < npos) {
            float p = expf(s[j] - m);
            den += p;
            o += p * g_vc[((size_t)(l * NSTEP + j) * NR + n) * DM + col];
        }
    }
    store_split(g_aA1, g_aA2, n, col, 32, o / den);
}

// ---------------- residual + layernorm (writes h + splits); dorot block0 resets g_mm ----
__global__ void k_ln(const float* __restrict__ delta, const float* __restrict__ gg,
                     const float* __restrict__ bb, int dorot, int pos) {
    if (dorot && blockIdx.x == 0 && threadIdx.x == 0) { g_mm[0] = 0xFFFFFFFFu; g_mm[1] = 0u; }
    int warp = threadIdx.x >> 5, lane = threadIdx.x & 31;
    int n = blockIdx.x * 8 + warp;
    float v[8];
    float sum = 0.f;
    #pragma unroll
    for (int k = 0; k < 8; k++) {
        int c = k * 32 + lane;
        v[k] = g_h[(size_t)n * DM + c] + delta[(size_t)n * DM + c];
        sum += v[k];
    }
    #pragma unroll
    for (int o = 16; o > 0; o >>= 1) sum += __shfl_xor_sync(0xffffffffu, sum, o);
    float mu = sum / 256.f;
    float var = 0.f;
    #pragma unroll
    for (int k = 0; k < 8; k++) { float d = v[k] - mu; var += d * d; }
    #pragma unroll
    for (int o = 16; o > 0; o >>= 1) var += __shfl_xor_sync(0xffffffffu, var, o);
    var /= 256.f;
    float inv = 1.f / sqrtf(var + 1e-5f);
    #pragma unroll
    for (int k = 0; k < 8; k++) {
        int c = k * 32 + lane;
        float out = (v[k] - mu) * inv * gg[c] + bb[c];
        g_h[(size_t)n * DM + c] = out;
        store_split(g_hA1, g_hA2, n, c, 32, out);
        if (dorot) {
            float p = __shfl_xor_sync(0xffffffffu, out, 1);
            float2 cs = g_ropetab[pos * 128 + (c >> 1)];
            float sgn = (c & 1) ? 1.f : -1.f;
            float vr = out * cs.x + sgn * p * cs.y;
            store_split(g_rA1, g_rA2, n, c, 32, vr);
        }
    }
}

// ---------------- out projection (N x 9) + fused min/max + hist clear ----------------
__global__ void k_outproj(const float* __restrict__ out_w, const float* __restrict__ out_b) {
    __shared__ unsigned szn[8], szx[8];
    // clear histograms for the fused k_bins atomics (stream-ordered before k_bins)
    {
        int idx = blockIdx.x * 256 + threadIdx.x;   // 0 .. NR*... (4096 blocks)
        if (idx < VOC * KL) g_Hc[idx] = 0.f;
        if (idx < VOC) g_Hm1[idx] = 0.f;
    }
    int warp = threadIdx.x >> 5, lane = threadIdx.x & 31;
    int n = blockIdx.x * 8 + warp;
    float hv[8];
    #pragma unroll
    for (int k = 0; k < 8; k++) hv[k] = g_h[(size_t)n * DM + k * 32 + lane];
    #pragma unroll
    for (int j = 0; j < 9; j++) {
        float acc = 0.f;
        #pragma unroll
        for (int k = 0; k < 8; k++) acc += hv[k] * out_w[j * DM + k * 32 + lane];
        #pragma unroll
        for (int o = 16; o > 0; o >>= 1) acc += __shfl_xor_sync(0xffffffffu, acc, o);
        if (lane == 0) {
            g_z[n * 9 + j] = acc + out_b[j];
            if (j == 0) { unsigned e = f2u(acc + out_b[0]); szn[warp] = e; szx[warp] = e; }
        }
    }
    __syncthreads();
    if (threadIdx.x == 0) {
        unsigned mn = szn[0], mx = szx[0];
        #pragma unroll
        for (int w = 1; w < 8; w++) {
            mn = (szn[w] < mn) ? szn[w] : mn;
            mx = (szx[w] > mx) ? szx[w] : mx;
        }
        atomicMin(&g_mm[0], mn);
        atomicMax(&g_mm[1], mx);
    }
}

// ---------------- bin assignment + fused histogram atomics ----------------
__global__ void k_bins(int step) {
    int n = blockIdx.x * blockDim.x + threadIdx.x;
    float MN = u2f(g_mm[0]);
    float MX = u2f(g_mm[1]);
    float x = g_z[n * 9];
    float bb[7];
    #pragma unroll
    for (int j = 0; j < 7; j++) bb[j] = g_z[n * 9 + 1 + j];
    int bin = -1;
    float xq = 0.f;
    #pragma unroll
    for (int j = 0; j < 8; j++) {
        float l = (j == 0) ? MN - 0.01f : bb[j - 1];
        float r = (j == 7) ? MX + 0.01f : bb[j];
        if (bin < 0 && x >= l && x < r && r > l) { bin = j; xq = (l + r) * 0.5f; }
    }
    g_bin[n] = bin;
    g_zarr[step * NR + n] = x;
    g_qarr[step * NR + n] = xq;
    // fused histogram (g_gid is pre-update; k_grad updates it later)
    int g = g_gid[n];
    if (g >= 0 && g < VOC) {
        if (bin >= 0) atomicAdd(&g_Hc[g * KL + bin], 1.f);
        else atomicAdd(&g_Hm1[g], 1.f);
    }
}

// ---------------- ratios update ----------------
__global__ void k_ratupd() {
    int v = blockIdx.x * 256 + threadIdx.x;
    #pragma unroll
    for (int k = 0; k < 7; k++) {
        float hc = g_Hc[v * KL + k];
        if (hc > 0.f) g_rat[v * KL + k] = hc;
    }
    float hc7 = g_Hc[v * KL + 7], hm = g_Hm1[v], old7 = g_rat[v * KL + 7];
    g_rat[v * KL + 7] = hc7 > 0.f ? hc7 : (hm > 0.f ? hm : old7);
}

// ---------------- grad dot + order clip ----------------
__global__ void __launch_bounds__(256) k_grad(int step) {
    __shared__ float sd[256], sc[256];
    int t = threadIdx.x;
    int n = blockIdx.x * 256 + t;
    int g = g_gid[n];
    g = g < 0 ? 0 : (g > VOC - 1 ? VOC - 1 : g);
    float r[8];
    #pragma unroll
    for (int k = 0; k < 8; k++) r[k] = g_rat[g * KL + k];
    float gr[7];
    float nrm = 0.f;
    #pragma unroll
    for (int k = 0; k < 7; k++) { gr[k] = -(r[k + 1] - r[k]); nrm += gr[k] * gr[k]; }
    nrm = sqrtf(nrm);
    float bby[7];
    #pragma unroll
    for (int k = 0; k < 7; k++) bby[k] = g_z[n * 9 + 1 + k];
    float dot = 0.f;
    #pragma unroll
    for (int k = 0; k < 7; k++) dot += bby[k] * (gr[k] / nrm);
    float cl = 0.f;
    #pragma unroll
    for (int k = 0; k < 6; k++) {
        float d = bby[k + 1] - bby[k];
        d = fmaxf(d, -9999999.f);
        d = fminf(d, 0.1f);
        cl += d;
    }
    int bin = g_bin[n];
    g_gid[n] += bin * (1 << (3 * step));
    g_code[n] = (float)bin;
    sd[t] = dot; sc[t] = cl;
    __syncthreads();
    for (int s = 128; s > 0; s >>= 1) {
        if (t < s) { sd[t] += sd[t + s]; sc[t] += sc[t + s]; }
        __syncthreads();
    }
    if (t == 0) { g_pdot[blockIdx.x] = sd[0]; g_pclip[blockIdx.x] = sc[0]; }
}

__global__ void k_losses() {
    __shared__ float sd[128], sc[128];
    int t = threadIdx.x;
    sd[t] = g_pdot[t]; sc[t] = g_pclip[t];
    __syncthreads();
    for (int s = 64; s > 0; s >>= 1) {
        if (t < s) { sd[t] += sd[t + s]; sc[t] += sc[t + s]; }
        __syncthreads();
    }
    if (t == 0) g_uni += sd[0] / (float)NR - sc[0] / ((float)NR * 6.f);
}

// ---------------- vq loss partials ----------------
__global__ void k_vqpart() {
    __shared__ float s[256];
    int t = threadIdx.x;
    int n = blockIdx.x * 256 + t;
    float acc = 0.f;
    #pragma unroll
    for (int j = 0; j < NSTEP; j++) {
        float d = g_qarr[j * NR + n] - g_zarr[j * NR + n];
        acc += d * d;
    }
    s[t] = acc;
    __syncthreads();
    for (int r = 128; r > 0; r >>= 1) {
        if (t < r) s[t] += s[t + r];
        __syncthreads();
    }
    if (t == 0) g_pvq[blockIdx.x] = s[0];
}

// ---------------- final projection ----------------
__global__ void k_zq(const float* __restrict__ ppw, const float* __restrict__ ppb,
                     float* __restrict__ out) {
    int t = blockIdx.x * blockDim.x + threadIdx.x;
    int b = t >> 15;
    int rem = t & 32767;
    int cz = rem >> 10;
    int l = rem & 1023;
    int n = (b << 10) + l;
    float acc = ppb[cz];
    #pragma unroll
    for (int j = 0; j < 4; j++) {
        float q = g_qarr[j * NR + n], z = g_zarr[j * NR + n];
        float s = (q + z) - z;
        acc += s * ppw[cz * 4 + j];
    }
    out[t] = acc;
}

__global__ void k_scalars(float* __restrict__ out, int out_size) {
    __shared__ float s[128];
    int t = threadIdx.x;
    s[t] = g_pvq[t];
    __syncthreads();
    for (int r = 64; r > 0; r >>= 1) {
        if (t < r) s[t] += s[t + r];
        __syncthreads();
    }
    if (t == 0) {
        out[out_size - 2] = s[0] / (float)(NR * NSTEP);
        out[out_size - 1] = g_uni;
    }
}

// ---------------- host ----------------
static void gemm_mma(const float* ah1, const float* ah2, const float* ar1, const float* ar2,
                     const float* w1, const float* w2, const float* bias,
                     float* C0, float* C1, float* C2, int seg,
                     int N, int K, int relu, int ropeN,
                     int osplit, float* O1, float* O2, int oKs) {
    dim3 grid(N / 64, NR / 128);
    k_gemm_mma<<<grid, 256, SMEM_MMA>>>(ah1, ah2, ar1, ar2, w1, w2, bias,
                                        C0, C1, C2, seg, N, K, relu, ropeN,
                                        osplit, O1, O2, oKs);
}

extern "C" void kernel_launch(void* const* d_in, const int* in_sizes, int n_in,
                              void* d_out, int out_size) {
    const float* x     = (const float*)d_in[0];
    const float* ppvw  = (const float*)d_in[1];
    const float* ppvb  = (const float*)d_in[2];
    const float* ppow  = (const float*)d_in[3];
    const float* ppob  = (const float*)d_in[4];
    const float* in_w  = (const float*)d_in[5];
    const float* in_b  = (const float*)d_in[6];
    const float* out_w = (const float*)d_in[7];
    const float* out_b = (const float*)d_in[8];
    const float* qkv_w = (const float*)d_in[9];
    const float* qkv_b = (const float*)d_in[10];
    const float* ao_w  = (const float*)d_in[11];
    const float* ao_b  = (const float*)d_in[12];
    const float* f1_w  = (const float*)d_in[13];
    const float* f1_b  = (const float*)d_in[14];
    const float* f2_w  = (const float*)d_in[15];
    const float* f2_b  = (const float*)d_in[16];
    const float* ln1g  = (const float*)d_in[17];
    const float* ln1b  = (const float*)d_in[18];
    const float* ln2g  = (const float*)d_in[19];
    const float* ln2b  = (const float*)d_in[20];
    const float* rat0  = (const float*)d_in[21];
    float* out = (float*)d_out;

    cudaFuncSetAttribute(k_gemm_mma, cudaFuncAttributeMaxDynamicSharedMemorySize, SMEM_MMA);

    float *h, *qb, *d1, *kc, *vc, *w1, *w2;
    float *hA1, *hA2, *rA1, *rA2, *aA1, *aA2, *dA1, *dA2;
    cudaGetSymbolAddress((void**)&h,   g_h);
    cudaGetSymbolAddress((void**)&qb,  g_qbuf);
    cudaGetSymbolAddress((void**)&d1,  g_d1);
    cudaGetSymbolAddress((void**)&kc,  g_kc);
    cudaGetSymbolAddress((void**)&vc,  g_vc);
    cudaGetSymbolAddress((void**)&w1,  g_w1);
    cudaGetSymbolAddress((void**)&w2,  g_w2);
    cudaGetSymbolAddress((void**)&hA1, g_hA1);
    cudaGetSymbolAddress((void**)&hA2, g_hA2);
    cudaGetSymbolAddress((void**)&rA1, g_rA1);
    cudaGetSymbolAddress((void**)&rA2, g_rA2);
    cudaGetSymbolAddress((void**)&aA1, g_aA1);
    cudaGetSymbolAddress((void**)&aA2, g_aA2);
    cudaGetSymbolAddress((void**)&dA1, g_dA1);
    cudaGetSymbolAddress((void**)&dA2, g_dA2);

    k_init<<<NR / 256, 256>>>(x, ppvw, ppvb, rat0);
    for (int l = 0; l < NLAY; l++) {
        k_splitw2<<<(768 * DM) / 256, 256>>>(qkv_w + (size_t)l * 768 * DM,
                                             w1 + OFF_QKV + (size_t)l * 768 * DM,
                                             w2 + OFF_QKV + (size_t)l * 768 * DM, 768, DM);
        k_splitw2<<<(DM * DM) / 256, 256>>>(ao_w + (size_t)l * DM * DM,
                                            w1 + OFF_AO + (size_t)l * DM * DM,
                                            w2 + OFF_AO + (size_t)l * DM * DM, DM, DM);
        k_splitw2<<<(FFD * DM) / 256, 256>>>(f1_w + (size_t)l * FFD * DM,
                                             w1 + OFF_F1 + (size_t)l * FFD * DM,
                                             w2 + OFF_F1 + (size_t)l * FFD * DM, FFD, DM);
        k_splitw2<<<(DM * FFD) / 256, 256>>>(f2_w + (size_t)l * DM * FFD,
                                             w1 + OFF_F2 + (size_t)l * DM * FFD,
                                             w2 + OFF_F2 + (size_t)l * DM * FFD, DM, FFD);
    }

    for (int i = 0; i < NSTEP; i++) {
        k_embed<<<NR * DM / 256, 256>>>(in_w, in_b, i);
        for (int l = 0; l < NLAY; l++) {
            const float* bl = qkv_b + l * 768;
            float* kslot = kc + (size_t)(l * NSTEP + i) * NR * DM;
            float* vslot = vc + (size_t)(l * NSTEP + i) * NR * DM;
            size_t oq = OFF_QKV + (size_t)l * 768 * DM;
            if (i == 0) {
                // step 0: Q unused (softmax over 1 position == 1) -> compute only K,V
                gemm_mma(hA1, hA2, rA1, rA2,
                         w1 + oq + 256 * DM, w2 + oq + 256 * DM, bl + 256,
                         kslot, vslot, nullptr, 256, 512, DM, 0, 256,
                         0, nullptr, nullptr, 0);
            } else {
                gemm_mma(hA1, hA2, rA1, rA2, w1 + oq, w2 + oq, bl,
                         qb, kslot, vslot, 256, 768, DM, 0, 512, 0, nullptr, nullptr, 0);
            }
            k_attn<<<NR, 256>>>(l, i + 1);
            size_t oa = OFF_AO + (size_t)l * DM * DM;
            gemm_mma(aA1, aA2, aA1, aA2, w1 + oa, w2 + oa, ao_b + l * DM,
                     d1, nullptr, nullptr, DM, DM, DM, 0, 0, 0, nullptr, nullptr, 0);
            k_ln<<<NR / 8, 256>>>(d1, ln1g + l * DM, ln1b + l * DM, 0, i);
            size_t of1 = OFF_F1 + (size_t)l * FFD * DM;
            gemm_mma(hA1, hA2, hA1, hA2, w1 + of1, w2 + of1, f1_b + l * FFD,
                     nullptr, nullptr, nullptr, FFD, FFD, DM, 1, 0, 1, dA1, dA2, 64);
            size_t of2 = OFF_F2 + (size_t)l * DM * FFD;
            gemm_mma(dA1, dA2, dA1, dA2, w1 + of2, w2 + of2, f2_b + l * DM,
                     d1, nullptr, nullptr, DM, DM, FFD, 0, 0, 0, nullptr, nullptr, 0);
            k_ln<<<NR / 8, 256>>>(d1, ln2g + l * DM, ln2b + l * DM, 1, i);
        }
        k_outproj<<<NR / 8, 256>>>(out_w, out_b);
        k_bins<<<NR / 256, 256>>>(i);
        k_ratupd<<<VOC / 256, 256>>>();
        k_grad<<<128, 256>>>(i);
        k_losses<<<1, 128>>>();
    }

    k_vqpart<<<128, 256>>>();
    k_zq<<<(NR * 32) / 256, 256>>>(ppow, ppob, out);
    k_scalars<<<1, 128>>>(out, out_size);
}